// round 1
// baseline (speedup 1.0000x reference)
#include <cuda_runtime.h>
#include <math.h>

#define L   512
#define T   96
#define CIN 150
#define HID 150
#define J3  450   // 3*H
#define KW  5

// ---- scratch (device globals; no allocation allowed) ----
__device__ float g_xi [T * L * J3];     // (t, l, 3H)  ~88.5 MB
__device__ float g_ys0[L * T * HID];    // layer-0 output, (l, t, h) ~29.5 MB
__device__ float g_hh5[KW * L * J3];    // per-tap partial hh, (tap, l, 3H) ~4.6 MB
__device__ float g_h  [2 * L * HID];    // ping-pong hidden state

// ---- tiling ----
#define BL   64
#define BJ   50
#define TY   16
#define TX   10
#define NTHR (TY * TX)   // 160 threads, each owns a 4x5 microtile

extern __shared__ float smem[];

__global__ void zero_kernel(float* __restrict__ p, int n) {
    int i = blockIdx.x * blockDim.x + threadIdx.x;
    if (i < n) p[i] = 0.f;
}

// xi[t][l][j] = bias[j] + sum_{tap,c} x[l+tap-2][t][c] * Wi[tap][c][j]
// x: (L, T, CIN), Wi: (KW, CIN, J3), out xi: (T, L, J3)
__global__ __launch_bounds__(NTHR) void xi_kernel(
    const float* __restrict__ x,
    const float* __restrict__ Wi,
    const float* __restrict__ bi,
    float* __restrict__ xi)
{
    float* sh_x = smem;                       // [(BL+4)][CIN]
    float* sh_w = smem + (BL + 4) * CIN;      // [CIN][BJ]

    const int t  = blockIdx.z;
    const int l0 = blockIdx.y * BL;
    const int j0 = blockIdx.x * BJ;
    const int tid = threadIdx.x;
    const int ty = tid / TX;
    const int tx = tid % TX;

    // load x halo rows (l0-2 .. l0+BL+1), zero-padded
    for (int idx = tid; idx < (BL + 4) * CIN; idx += NTHR) {
        int r = idx / CIN, c = idx % CIN;
        int l = l0 - 2 + r;
        sh_x[idx] = (l >= 0 && l < L) ? x[((size_t)l * T + t) * CIN + c] : 0.f;
    }

    float acc[4][5];
    #pragma unroll
    for (int i = 0; i < 4; i++)
        #pragma unroll
        for (int j = 0; j < 5; j++) acc[i][j] = 0.f;

    for (int tap = 0; tap < KW; tap++) {
        __syncthreads();   // protects sh_x (tap 0) and sh_w reuse (tap > 0)
        for (int idx = tid; idx < CIN * BJ; idx += NTHR) {
            int c = idx / BJ, j = idx % BJ;
            sh_w[idx] = Wi[((size_t)tap * CIN + c) * J3 + j0 + j];
        }
        __syncthreads();

        #pragma unroll 2
        for (int c = 0; c < CIN; c++) {
            float a[4], b[5];
            #pragma unroll
            for (int i = 0; i < 4; i++)
                a[i] = sh_x[(ty * 4 + i + tap) * CIN + c];
            #pragma unroll
            for (int j = 0; j < 5; j++)
                b[j] = sh_w[c * BJ + tx * 5 + j];
            #pragma unroll
            for (int i = 0; i < 4; i++)
                #pragma unroll
                for (int j = 0; j < 5; j++)
                    acc[i][j] += a[i] * b[j];
        }
    }

    #pragma unroll
    for (int j = 0; j < 5; j++) {
        float bb = bi[j0 + tx * 5 + j];
        #pragma unroll
        for (int i = 0; i < 4; i++) {
            int l = l0 + ty * 4 + i;
            xi[((size_t)t * L + l) * J3 + j0 + tx * 5 + j] = acc[i][j] + bb;
        }
    }
}

// Per-tap partial recurrent GEMM:
// hh5[tap][l][j] = sum_c h[l+tap-2][c] * Wh[tap][c][j]
__global__ __launch_bounds__(NTHR) void s1_kernel(
    const float* __restrict__ h,
    const float* __restrict__ Wh,
    float* __restrict__ hh5)
{
    float* sh_h = smem;                 // [BL][HID]
    float* sh_w = smem + BL * HID;      // [HID][BJ]

    const int tap = blockIdx.z;
    const int l0  = blockIdx.y * BL;
    const int j0  = blockIdx.x * BJ;
    const int tid = threadIdx.x;
    const int ty = tid / TX;
    const int tx = tid % TX;

    for (int idx = tid; idx < BL * HID; idx += NTHR) {
        int r = idx / HID, c = idx % HID;
        int l = l0 + r + tap - 2;
        sh_h[idx] = (l >= 0 && l < L) ? h[l * HID + c] : 0.f;
    }
    for (int idx = tid; idx < HID * BJ; idx += NTHR) {
        int c = idx / BJ, j = idx % BJ;
        sh_w[idx] = Wh[((size_t)tap * HID + c) * J3 + j0 + j];
    }
    __syncthreads();

    float acc[4][5];
    #pragma unroll
    for (int i = 0; i < 4; i++)
        #pragma unroll
        for (int j = 0; j < 5; j++) acc[i][j] = 0.f;

    #pragma unroll 2
    for (int c = 0; c < HID; c++) {
        float a[4], b[5];
        #pragma unroll
        for (int i = 0; i < 4; i++)
            a[i] = sh_h[(ty * 4 + i) * HID + c];
        #pragma unroll
        for (int j = 0; j < 5; j++)
            b[j] = sh_w[c * BJ + tx * 5 + j];
        #pragma unroll
        for (int i = 0; i < 4; i++)
            #pragma unroll
            for (int j = 0; j < 5; j++)
                acc[i][j] += a[i] * b[j];
    }

    #pragma unroll
    for (int i = 0; i < 4; i++) {
        int l = l0 + ty * 4 + i;
        #pragma unroll
        for (int j = 0; j < 5; j++)
            hh5[((size_t)tap * L + l) * J3 + j0 + tx * 5 + j] = acc[i][j];
    }
}

// Gate fusion: sums tap partials, applies GRU update, writes h_next and ys.
__global__ void s2_kernel(
    const float* __restrict__ xi_t,   // (L, J3) slice for this t
    const float* __restrict__ hh5,
    const float* __restrict__ h_in,
    float* __restrict__ h_out,
    float* __restrict__ ys,           // (L, T, HID)
    int t)
{
    int idx = blockIdx.x * blockDim.x + threadIdx.x;
    if (idx >= L * HID) return;
    int l = idx / HID, c = idx % HID;

    float hr = 0.f, hz = 0.f, hn = 0.f;
    #pragma unroll
    for (int tap = 0; tap < KW; tap++) {
        const float* p = hh5 + ((size_t)tap * L + l) * J3;
        hr += p[c];
        hz += p[c + HID];
        hn += p[c + 2 * HID];
    }
    const float* q = xi_t + (size_t)l * J3;
    float xr = q[c], xz = q[c + HID], xn = q[c + 2 * HID];

    float r = 1.f / (1.f + expf(-(xr + hr)));
    float z = 1.f / (1.f + expf(-(xz + hz)));
    float n = tanhf(xn + r * hn);
    float hnew = (1.f - z) * n + z * h_in[idx];

    h_out[idx] = hnew;
    ys[((size_t)l * T + t) * HID + c] = hnew;
}

extern "C" void kernel_launch(void* const* d_in, const int* in_sizes, int n_in,
                              void* d_out, int out_size)
{
    (void)in_sizes; (void)n_in; (void)out_size;
    const float* xs  = (const float*)d_in[0];
    const float* Wi0 = (const float*)d_in[1];
    const float* bi0 = (const float*)d_in[2];
    const float* Wh0 = (const float*)d_in[3];
    const float* Wi1 = (const float*)d_in[4];
    const float* bi1 = (const float*)d_in[5];
    const float* Wh1 = (const float*)d_in[6];
    float* out = (float*)d_out;

    float *xi, *ys0, *hh5, *h;
    cudaGetSymbolAddress((void**)&xi,  g_xi);
    cudaGetSymbolAddress((void**)&ys0, g_ys0);
    cudaGetSymbolAddress((void**)&hh5, g_hh5);
    cudaGetSymbolAddress((void**)&h,   g_h);

    const size_t smem_xi = ((BL + 4) * CIN + CIN * BJ) * sizeof(float); // 70800 B
    const size_t smem_s1 = (BL * HID + HID * BJ) * sizeof(float);       // 68400 B
    cudaFuncSetAttribute(xi_kernel, cudaFuncAttributeMaxDynamicSharedMemorySize, 73728);
    cudaFuncSetAttribute(s1_kernel, cudaFuncAttributeMaxDynamicSharedMemorySize, 73728);

    const dim3 grid_xi(J3 / BJ, L / BL, T);   // (9, 8, 96)
    const dim3 grid_s1(J3 / BJ, L / BL, KW);  // (9, 8, 5)
    const int  n_h = L * HID;
    const int  gate_blocks = (n_h + 255) / 256;

    for (int layer = 0; layer < 2; layer++) {
        const float* x  = layer ? (const float*)ys0 : xs;
        const float* Wi = layer ? Wi1 : Wi0;
        const float* bi = layer ? bi1 : bi0;
        const float* Wh = layer ? Wh1 : Wh0;
        float*       ys = layer ? out : ys0;

        zero_kernel<<<gate_blocks, 256>>>(h, n_h);
        xi_kernel<<<grid_xi, NTHR, smem_xi>>>(x, Wi, bi, xi);

        int cur = 0;
        for (int t = 0; t < T; t++) {
            s1_kernel<<<grid_s1, NTHR, smem_s1>>>(h + cur * n_h, Wh, hh5);
            s2_kernel<<<gate_blocks, 256>>>(xi + (size_t)t * L * J3, hh5,
                                            h + cur * n_h, h + (1 - cur) * n_h,
                                            ys, t);
            cur ^= 1;
        }
    }
}